// round 6
// baseline (speedup 1.0000x reference)
#include <cuda_runtime.h>
#include <cstdint>
#include <cstddef>

#define Bq 64
#define Sq 256
#define Hq 1024
#define Lq 4
#define H2q 2048
#define H3q 3072
#define NCTA 128
#define NTHR 512
#define NPH (Sq + Lq - 1)

// ---------------- persistent device scratch ----------------
__device__ float g_hbuf[2][Lq][Bq][Hq];   // parity double-buffered hidden (post-attn)
__device__ float g_hgru[Lq][Bq][Hq];      // GRU cell output (pre-attn)
__device__ float g_sorted[Lq][Bq][Hq];    // sorted GRU output
__device__ float g_a0[Lq][Bq][H2q];       // w0 output, stored PRE-SHUFFLED for w1
__device__ float g_a1[Lq][Bq][H2q];       // w1 output, stored PRE-SHUFFLED for w2
__device__ float g_a2[Lq][Bq][H2q];       // relu(w2) output, linear
__device__ unsigned g_cnt = 0;
__device__ volatile unsigned g_gen = 0;

// ---------------- smem ----------------
struct SmemGRU { uint32_t As[2][64][36]; uint32_t Bs[2][3][32][36]; };  // 46080 B
struct SmemFC  { uint32_t As[2][64][36]; uint32_t Bs[2][64][36]; };     // 36864 B
struct SmemEpi { float E[4][64][32]; };                                 // 32768 B
struct SmemSort{ float s[2][1024]; };                                   //  8192 B
union SmemAll  { SmemGRU g; SmemFC f; SmemEpi e; SmemSort so; };

// ---------------- helpers ----------------
__device__ __forceinline__ uint32_t f2tf(float f) {
    uint32_t u;
    asm("cvt.rna.tf32.f32 %0, %1;" : "=r"(u) : "f"(f));
    return u;
}
__device__ __forceinline__ void mma8(float* c, uint32_t a0, uint32_t a1, uint32_t a2, uint32_t a3,
                                     uint32_t b0, uint32_t b1) {
    asm volatile(
        "mma.sync.aligned.m16n8k8.row.col.f32.tf32.tf32.f32 "
        "{%0,%1,%2,%3},{%4,%5,%6,%7},{%8,%9},{%0,%1,%2,%3};"
        : "+f"(c[0]), "+f"(c[1]), "+f"(c[2]), "+f"(c[3])
        : "r"(a0), "r"(a1), "r"(a2), "r"(a3), "r"(b0), "r"(b1));
}
__device__ __forceinline__ float sigmoidf_(float x) { return 1.0f / (1.0f + __expf(-x)); }
__device__ __forceinline__ float4 ldg4(const float* p)  { return __ldg((const float4*)p); }
__device__ __forceinline__ float4 ldcg4(const float* p) { return __ldcg((const float4*)p); }

// ---------------- grid barrier (128 co-resident CTAs) ----------------
__device__ __forceinline__ void gridbar() {
    __threadfence();
    __syncthreads();
    if (threadIdx.x == 0) {
        unsigned gen = g_gen;
        if (atomicAdd(&g_cnt, 1u) == NCTA - 1) {
            g_cnt = 0;
            __threadfence();
            g_gen = gen + 1;
        } else {
            while (g_gen == gen) __nanosleep(64);
        }
    }
    __syncthreads();
}

// ---------------- GRU tile: 32 H-cols, 4 warp-groups stream R/Z/Ni/Nh ----------
__device__ __forceinline__ void gru_tile(SmemAll* sm, int l, int t, int n0,
    const float* __restrict__ x, const float* __restrict__ Wih,
    const float* __restrict__ Whh, const float* __restrict__ bih,
    const float* __restrict__ bhh)
{
    const int par = t & 1;
    const int tid = threadIdx.x;
    const int warp = tid >> 5, lane = tid & 31;
    const int ws = warp >> 2, wm = warp & 3;       // stream, m-block(16 rows)
    const int grp = lane >> 2, tig = lane & 3;

    const float* Wl_ih = Wih + (size_t)l * H3q * Hq;
    const float* Wl_hh = Whh + (size_t)l * H3q * Hq;
    const float* hlm1  = &g_hbuf[par][(l == 0 ? 0 : l - 1)][0][0];
    const float* hprev = &g_hbuf[par ^ 1][l][0][0];

    const int ar = tid >> 3, ak4 = (tid & 7) << 2;         // A: 64 rows x 32 cols
    const int bs0 = tid >> 8, brow0 = (tid >> 3) & 31, bk0 = (tid & 7) << 2;
    const int bf1 = tid + 512;
    const int bs1 = bf1 >> 8, brow1 = (bf1 >> 3) & 31, bk1 = (bf1 & 7) << 2;
    const bool bv1 = (tid < 256);

    float acc[4][4] = {};
    float4 ra, rb0, rb1;

#define GRU_LOAD(c) { \
        int k_ = (c) * 32 + ak4; \
        if (k_ < Hq) { \
            if (l == 0) ra = ldg4(x + ((size_t)ar * Sq + t) * Hq + k_); \
            else        ra = ldcg4(hlm1 + (size_t)ar * Hq + k_); \
        } else ra = ldcg4(hprev + (size_t)ar * Hq + (k_ - Hq)); \
        const float* mat_ = ((c) < 32) ? Wl_ih : Wl_hh; \
        int kc_ = ((c) * 32) & (Hq - 1); \
        rb0 = ldg4(mat_ + (size_t)(bs0 * Hq + n0 + brow0) * Hq + kc_ + bk0); \
        if (bv1) rb1 = ldg4(mat_ + (size_t)(bs1 * Hq + n0 + brow1) * Hq + kc_ + bk1); \
    }
#define GRU_STS(buf) { \
        uint4 u_; \
        u_.x = f2tf(ra.x); u_.y = f2tf(ra.y); u_.z = f2tf(ra.z); u_.w = f2tf(ra.w); \
        *(uint4*)&sm->g.As[buf][ar][ak4] = u_; \
        u_.x = f2tf(rb0.x); u_.y = f2tf(rb0.y); u_.z = f2tf(rb0.z); u_.w = f2tf(rb0.w); \
        *(uint4*)&sm->g.Bs[buf][bs0][brow0][bk0] = u_; \
        if (bv1) { \
            u_.x = f2tf(rb1.x); u_.y = f2tf(rb1.y); u_.z = f2tf(rb1.z); u_.w = f2tf(rb1.w); \
            *(uint4*)&sm->g.Bs[buf][bs1][brow1][bk1] = u_; \
        } \
    }

    GRU_LOAD(0); GRU_STS(0);
    __syncthreads();
    for (int c = 0; c < 64; c++) {
        const int buf = c & 1;
        if (c < 63) GRU_LOAD(c + 1);
        const bool on = (ws < 2) || (ws == 2 && c < 32) || (ws == 3 && c >= 32);
        if (on) {
            const int bsel = (ws < 2) ? ws : 2;
#pragma unroll
            for (int kk = 0; kk < 32; kk += 8) {
                uint32_t a0 = sm->g.As[buf][wm * 16 + grp][kk + tig];
                uint32_t a1 = sm->g.As[buf][wm * 16 + grp + 8][kk + tig];
                uint32_t a2 = sm->g.As[buf][wm * 16 + grp][kk + tig + 4];
                uint32_t a3 = sm->g.As[buf][wm * 16 + grp + 8][kk + tig + 4];
#pragma unroll
                for (int ns = 0; ns < 4; ns++)
                    mma8(acc[ns], a0, a1, a2, a3,
                         sm->g.Bs[buf][bsel][ns * 8 + grp][kk + tig],
                         sm->g.Bs[buf][bsel][ns * 8 + grp][kk + tig + 4]);
            }
        }
        if (c < 63) GRU_STS(buf ^ 1);
        __syncthreads();
    }
#undef GRU_LOAD
#undef GRU_STS

    // stage per-stream accumulators, then combine gates
#pragma unroll
    for (int ns = 0; ns < 4; ns++)
#pragma unroll
        for (int e = 0; e < 4; e++)
            sm->e.E[ws][wm * 16 + grp + ((e >> 1) << 3)][ns * 8 + tig * 2 + (e & 1)] = acc[ns][e];
    __syncthreads();

    const float* bi = bih + l * H3q;
    const float* bh = bhh + l * H3q;
#pragma unroll
    for (int e = 0; e < 4; e++) {
        int q = tid + e * 512;
        int m = q >> 5, n = q & 31, col = n0 + n;
        float r  = sigmoidf_(sm->e.E[0][m][n] + __ldg(bi + col) + __ldg(bh + col));
        float z  = sigmoidf_(sm->e.E[1][m][n] + __ldg(bi + Hq + col) + __ldg(bh + Hq + col));
        float nn = tanhf(sm->e.E[2][m][n] + __ldg(bi + 2 * Hq + col)
                         + r * (sm->e.E[3][m][n] + __ldg(bh + 2 * Hq + col)));
        float hp = __ldcg(&g_hbuf[par ^ 1][l][m][col]);
        g_hgru[l][m][col] = (1.0f - z) * nn + z * hp;
    }
}

// ---------------- 2-rows-per-CTA bitonic sort (ascending, 1024 each) ------------
__device__ __forceinline__ void sort_rows(SmemAll* sm, int l, int pair) {
    const int tid = threadIdx.x;
    const int sub = tid >> 8, tt = tid & 255;
    const int b = pair * 2 + sub;
    float* s = sm->so.s[sub];
#pragma unroll
    for (int e = 0; e < 4; e++) s[tt + (e << 8)] = __ldcg(&g_hgru[l][b][tt + (e << 8)]);
    __syncthreads();
    for (int k = 2; k <= 1024; k <<= 1) {
        for (int j = k >> 1; j > 0; j >>= 1) {
#pragma unroll
            for (int e = 0; e < 2; e++) {
                int tc = tt + (e << 8);
                int pos = ((tc & ~(j - 1)) << 1) | (tc & (j - 1));
                int q = pos | j;
                bool up = ((pos & k) == 0);
                float a = s[pos], bb = s[q];
                if ((a > bb) == up) { s[pos] = bb; s[q] = a; }
            }
            __syncthreads();
        }
    }
#pragma unroll
    for (int e = 0; e < 4; e++) g_sorted[l][b][tt + (e << 8)] = s[tt + (e << 8)];
    __syncthreads();
}

// ---------------- generic FC tile ----------------
// MODE 0: a0 = [h|sorted] @ w0^T (K=1024, NT=64) -> stored shuffled
// MODE 1: a1 = a0s @ w1^T        (K=512,  NT=64) -> stored shuffled
// MODE 2: a2 = relu(a1s @ w2^T)  (K=512,  NT=64) -> linear
// MODE 3: h' = hgru*sigmoid(a2@w3^T) (K=2048, NT=32) -> hbuf + outs(l==3)
template <int MODE>
__device__ __forceinline__ void fc_tile(SmemAll* sm, int l, int t, int n0,
    const float* __restrict__ Wall, float* __restrict__ outp)
{
    constexpr int NT = (MODE == 3) ? 32 : 64;
    constexpr int KT = (MODE == 0) ? 1024 : ((MODE == 3) ? 2048 : 512);
    constexpr int NC = KT / 32;
    constexpr int NSUB = NT / 32;
    const int tid = threadIdx.x;
    const int warp = tid >> 5, lane = tid & 31;
    const int wm = warp & 3, wn = warp >> 2;
    const int grp = lane >> 2, tig = lane & 3;

    const float* Abase; int astride, aoff = 0;
    if constexpr (MODE == 0)      { Abase = (n0 >= Hq) ? &g_sorted[l][0][0] : &g_hgru[l][0][0]; astride = Hq; }
    else if constexpr (MODE == 1) { Abase = &g_a0[l][0][0]; astride = H2q; aoff = (n0 >> 9) << 9; }
    else if constexpr (MODE == 2) { Abase = &g_a1[l][0][0]; astride = H2q; aoff = (n0 >> 9) << 9; }
    else                          { Abase = &g_a2[l][0][0]; astride = H2q; }

    const float* Wl; int o0;
    if constexpr (MODE == 0)                   { Wl = Wall + (size_t)l * Hq * Hq;   o0 = n0 & (Hq - 1); }
    else if constexpr (MODE == 1 || MODE == 2) { Wl = Wall + (size_t)l * 512 * 512; o0 = n0 & 511; }
    else                                       { Wl = Wall + (size_t)l * Hq * H2q;  o0 = n0; }

    const int ar = tid >> 3, ak4 = (tid & 7) << 2;
    const int brow = tid >> 3, bk4 = (tid & 7) << 2;
    const bool bval = tid < NT * 8;

    float acc[NSUB][4];
#pragma unroll
    for (int i = 0; i < NSUB; i++) { acc[i][0] = acc[i][1] = acc[i][2] = acc[i][3] = 0.f; }
    float4 ra, rb;

#define FC_LOAD(c) { \
        ra = ldcg4(Abase + (size_t)ar * astride + aoff + (c) * 32 + ak4); \
        if (bval) rb = ldg4(Wl + (size_t)(o0 + brow) * KT + (c) * 32 + bk4); \
    }
#define FC_STS(buf) { \
        uint4 u_; u_.x = f2tf(ra.x); u_.y = f2tf(ra.y); u_.z = f2tf(ra.z); u_.w = f2tf(ra.w); \
        *(uint4*)&sm->f.As[buf][ar][ak4] = u_; \
        if (bval) { \
            u_.x = f2tf(rb.x); u_.y = f2tf(rb.y); u_.z = f2tf(rb.z); u_.w = f2tf(rb.w); \
            *(uint4*)&sm->f.Bs[buf][brow][bk4] = u_; \
        } \
    }

    FC_LOAD(0); FC_STS(0);
    __syncthreads();
    for (int c = 0; c < NC; c++) {
        const int buf = c & 1;
        if (c < NC - 1) FC_LOAD(c + 1);
#pragma unroll
        for (int kk = 0; kk < 32; kk += 8) {
            uint32_t a0 = sm->f.As[buf][wm * 16 + grp][kk + tig];
            uint32_t a1 = sm->f.As[buf][wm * 16 + grp + 8][kk + tig];
            uint32_t a2 = sm->f.As[buf][wm * 16 + grp][kk + tig + 4];
            uint32_t a3 = sm->f.As[buf][wm * 16 + grp + 8][kk + tig + 4];
#pragma unroll
            for (int ns = 0; ns < NSUB; ns++) {
                int nb = wn * (NT / 4) + ns * 8 + grp;
                mma8(acc[ns], a0, a1, a2, a3,
                     sm->f.Bs[buf][nb][kk + tig], sm->f.Bs[buf][nb][kk + tig + 4]);
            }
        }
        if (c < NC - 1) FC_STS(buf ^ 1);
        __syncthreads();
    }
#undef FC_LOAD
#undef FC_STS

#pragma unroll
    for (int ns = 0; ns < NSUB; ns++)
#pragma unroll
        for (int e = 0; e < 4; e++) {
            int row = wm * 16 + grp + ((e >> 1) << 3);
            int cl = wn * (NT / 4) + ns * 8 + tig * 2 + (e & 1);
            int cg = n0 + cl;
            float v = acc[ns][e];
            if constexpr (MODE == 0)      g_a0[l][row][4 * (cg & 511) + (cg >> 9)] = v;
            else if constexpr (MODE == 1) g_a1[l][row][4 * (cg & 511) + (cg >> 9)] = v;
            else if constexpr (MODE == 2) g_a2[l][row][cg] = fmaxf(v, 0.0f);
            else {
                float val = __ldcg(&g_hgru[l][row][cg]) * sigmoidf_(v);
                g_hbuf[t & 1][l][row][cg] = val;
                if (l == Lq - 1)
                    outp[((size_t)row * Sq + t) * Hq + cg] = val;
            }
        }
}

// ---------------- the single persistent kernel ----------------
__global__ void __launch_bounds__(NTHR, 1) fss_persist_kernel(
    const float* __restrict__ x, const float* __restrict__ h0,
    const float* __restrict__ Wih, const float* __restrict__ Whh,
    const float* __restrict__ bih, const float* __restrict__ bhh,
    const float* __restrict__ aw0, const float* __restrict__ aw1,
    const float* __restrict__ aw2, const float* __restrict__ aw3,
    float* __restrict__ outp, int out_size)
{
    __shared__ SmemAll sm;
    const int bx = blockIdx.x, tid = threadIdx.x;

    // init hidden into parity-1 buffer (t=0 reads parity (t-1)&1 == 1)
    for (int i = bx * NTHR + tid; i < Lq * Bq * Hq; i += NCTA * NTHR) {
        int l = i >> 16;            // Bq*Hq = 65536
        int k = i & (Hq - 1);
        (&g_hbuf[1][0][0][0])[i] = h0[l * Hq + k];
    }
    gridbar();

    const int l = bx >> 5, idx = bx & 31;
    for (int p = 0; p < NPH; ++p) {
        const int t = p - l;
        const bool act = (t >= 0 && t < Sq);
        if (act) gru_tile(&sm, l, t, idx * 32, x, Wih, Whh, bih, bhh);
        gridbar();
        if (act) sort_rows(&sm, l, idx);
        gridbar();
        if (act) fc_tile<0>(&sm, l, t, idx * 64, aw0, outp);
        gridbar();
        if (act) fc_tile<1>(&sm, l, t, idx * 64, aw1, outp);
        gridbar();
        if (act) fc_tile<2>(&sm, l, t, idx * 64, aw2, outp);
        gridbar();
        if (act) fc_tile<3>(&sm, l, t, idx * 32, aw3, outp);
        gridbar();
    }

    // final hidden state hT (t=255 -> parity 1), layout (L,B,H)
    if (out_size >= Bq * Sq * Hq + Lq * Bq * Hq) {
        for (int i = bx * NTHR + tid; i < Lq * Bq * Hq; i += NCTA * NTHR)
            outp[(size_t)Bq * Sq * Hq + i] = __ldcg(&(&g_hbuf[1][0][0][0])[i]);
    }
}

// ---------------- launch ----------------
extern "C" void kernel_launch(void* const* d_in, const int* in_sizes, int n_in,
                              void* d_out, int out_size) {
    (void)in_sizes; (void)n_in;
    fss_persist_kernel<<<NCTA, NTHR>>>(
        (const float*)d_in[0], (const float*)d_in[1],
        (const float*)d_in[2], (const float*)d_in[3],
        (const float*)d_in[4], (const float*)d_in[5],
        (const float*)d_in[6], (const float*)d_in[7],
        (const float*)d_in[8], (const float*)d_in[9],
        (float*)d_out, out_size);
}

// round 7
// speedup vs baseline: 1.7307x; 1.7307x over previous
#include <cuda_runtime.h>
#include <cstdint>
#include <cstddef>

#define Bq 64
#define Sq 256
#define Hq 1024
#define Lq 4
#define H2q 2048
#define H3q 3072
#define NCTA 128
#define NTHR 512
#define NPH (Sq + Lq - 1)
#define KC 64
#define STR 68
#define DP 4
#define STAGE_G ((64 + 96) * STR)            // floats per GRU pipeline stage
#define SMEM_BYTES (DP * STAGE_G * 4)        // 174080 B

// ---------------- persistent device scratch ----------------
__device__ __align__(16) float g_hbuf[2][Lq][Bq][Hq];
__device__ __align__(16) float g_hgru[Lq][Bq][Hq];
__device__ __align__(16) float g_sorted[Lq][Bq][Hq];
__device__ __align__(16) float g_a0[Lq][Bq][H2q];
__device__ __align__(16) float g_a1[Lq][Bq][H2q];
__device__ __align__(16) float g_a2[Lq][Bq][H2q];
// tf32-pre-rounded weights (consumed as raw bits by mma)
__device__ __align__(16) float g_wih[Lq * H3q * Hq];
__device__ __align__(16) float g_whh[Lq * H3q * Hq];
__device__ __align__(16) float g_w0[Lq * Hq * Hq];
__device__ __align__(16) float g_w1[Lq * 512 * 512];
__device__ __align__(16) float g_w2[Lq * 512 * 512];
__device__ __align__(16) float g_w3[Lq * Hq * H2q];

__device__ unsigned g_cnt = 0;
__device__ volatile unsigned g_gen = 0;
__device__ unsigned g_lcnt[Lq] = {0, 0, 0, 0};
__device__ volatile unsigned g_lgen[Lq] = {0, 0, 0, 0};

// ---------------- helpers ----------------
__device__ __forceinline__ uint32_t f2tf(float f) {
    uint32_t u;
    asm("cvt.rna.tf32.f32 %0, %1;" : "=r"(u) : "f"(f));
    return u;
}
__device__ __forceinline__ float tftrunc(float f) { return __uint_as_float(f2tf(f)); }
__device__ __forceinline__ void mma8(float* c, uint32_t a0, uint32_t a1, uint32_t a2, uint32_t a3,
                                     uint32_t b0, uint32_t b1) {
    asm volatile(
        "mma.sync.aligned.m16n8k8.row.col.f32.tf32.tf32.f32 "
        "{%0,%1,%2,%3},{%4,%5,%6,%7},{%8,%9},{%0,%1,%2,%3};"
        : "+f"(c[0]), "+f"(c[1]), "+f"(c[2]), "+f"(c[3])
        : "r"(a0), "r"(a1), "r"(a2), "r"(a3), "r"(b0), "r"(b1));
}
__device__ __forceinline__ float sigmoidf_(float x) { return 1.0f / (1.0f + __expf(-x)); }

__device__ __forceinline__ void cpa16(void* dst, const void* src) {
    uint32_t d = (uint32_t)__cvta_generic_to_shared(dst);
    asm volatile("cp.async.cg.shared.global [%0], [%1], 16;" :: "r"(d), "l"(src));
}
#define CP_COMMIT() asm volatile("cp.async.commit_group;")
__device__ __forceinline__ void cpwait(int left) {
    if (left >= 2)      asm volatile("cp.async.wait_group 2;");
    else if (left == 1) asm volatile("cp.async.wait_group 1;");
    else                asm volatile("cp.async.wait_group 0;");
}

// ---------------- barriers ----------------
__device__ __forceinline__ void gridbar() {
    __threadfence();
    __syncthreads();
    if (threadIdx.x == 0) {
        unsigned gen = g_gen;
        if (atomicAdd(&g_cnt, 1u) == NCTA - 1) {
            g_cnt = 0;
            __threadfence();
            g_gen = gen + 1;
        } else {
            while (g_gen == gen) __nanosleep(64);
        }
    }
    __syncthreads();
}
__device__ __forceinline__ void layerbar(int l) {
    __threadfence();
    __syncthreads();
    if (threadIdx.x == 0) {
        unsigned gen = g_lgen[l];
        if (atomicAdd(&g_lcnt[l], 1u) == 31) {
            g_lcnt[l] = 0;
            __threadfence();
            g_lgen[l] = gen + 1;
        } else {
            while (g_lgen[l] == gen) __nanosleep(32);
        }
    }
    __syncthreads();
}

// ---------------- weight conversion (fp32 -> tf32-rounded fp32) ----------------
__device__ __forceinline__ void conv_tf(float* dst, const float* src, int n4, int gid, int gsz) {
    for (int i = gid; i < n4; i += gsz) {
        float4 v = __ldg((const float4*)src + i);
        uint4 u;
        u.x = f2tf(v.x); u.y = f2tf(v.y); u.z = f2tf(v.z); u.w = f2tf(v.w);
        ((uint4*)dst)[i] = u;
    }
}

// ---------------- GRU stage: 32 H-cols/CTA, 6 warps of m32n32 ----------------
__device__ __forceinline__ void gru_stage(float* dyn, int l, int t, int n0,
    const float* __restrict__ x,
    const float* __restrict__ bih, const float* __restrict__ bhh)
{
    const int par = t & 1;
    const int tid = threadIdx.x;
    const int warp = tid >> 5, lane = tid & 31;
    const int st = warp >> 1, wm = warp & 1;      // stream (0=R,1=Z,2=N), m32-block
    const int grp = lane >> 2, tig = lane & 3;

    const float* Wl_ih = g_wih + (size_t)l * H3q * Hq;
    const float* Wl_hh = g_whh + (size_t)l * H3q * Hq;
    const float* hlm1  = &g_hbuf[par][(l == 0 ? 0 : l - 1)][0][0];
    const float* hprev = &g_hbuf[par ^ 1][l][0][0];

    auto issue = [&](int c, int s) {
        float* A = dyn + s * STAGE_G;
        float* B = A + 64 * STR;
        const int k0 = c * KC;
        const float* mat = (c < 16) ? Wl_ih : Wl_hh;
        const int kc = k0 & (Hq - 1);
#pragma unroll
        for (int i = 0; i < 2; i++) {
            int idx = tid + i * 512;
            int row = idx >> 4, c4 = (idx & 15) << 2;
            int k = k0 + c4;
            const float* src;
            if (k < Hq) src = (l == 0) ? x + ((size_t)row * Sq + t) * Hq + k
                                       : hlm1 + (size_t)row * Hq + k;
            else        src = hprev + (size_t)row * Hq + (k - Hq);
            cpa16(A + row * STR + c4, src);
        }
#pragma unroll
        for (int i = 0; i < 3; i++) {
            int idx = tid + i * 512;
            int br = idx >> 4, c4 = (idx & 15) << 2;
            int strm = br >> 5, rw = br & 31;
            cpa16(B + br * STR + c4,
                  mat + ((size_t)(strm * Hq + n0 + rw)) * Hq + kc + c4);
        }
        CP_COMMIT();
    };

    float acc[2][2][4][4];                        // [sel Ni/Nh][mt][ns][e]
#pragma unroll
    for (int a = 0; a < 2; a++)
#pragma unroll
        for (int b = 0; b < 2; b++)
#pragma unroll
            for (int cc = 0; cc < 4; cc++)
#pragma unroll
                for (int d = 0; d < 4; d++) acc[a][b][cc][d] = 0.0f;

    issue(0, 0); issue(1, 1); issue(2, 2);
    const int NC = 32;
    for (int c = 0; c < NC; c++) {
        const int s = c & 3;
        cpwait(NC - 1 - c);
        __syncthreads();
        if (c + 3 < NC) issue(c + 3, (c + 3) & 3);
        if (warp < 6) {
            const int sel = (st == 2 && c >= 16) ? 1 : 0;
            const float* A = dyn + s * STAGE_G;
            const uint32_t* B = (const uint32_t*)(dyn + s * STAGE_G + 64 * STR + st * 32 * STR);
#pragma unroll
            for (int kk = 0; kk < KC; kk += 8) {
                uint32_t a[2][4];
#pragma unroll
                for (int mt = 0; mt < 2; mt++) {
                    int r0 = wm * 32 + mt * 16 + grp;
                    a[mt][0] = f2tf(A[r0 * STR + kk + tig]);
                    a[mt][1] = f2tf(A[(r0 + 8) * STR + kk + tig]);
                    a[mt][2] = f2tf(A[r0 * STR + kk + tig + 4]);
                    a[mt][3] = f2tf(A[(r0 + 8) * STR + kk + tig + 4]);
                }
#pragma unroll
                for (int ns = 0; ns < 4; ns++) {
                    uint32_t b0 = B[(ns * 8 + grp) * STR + kk + tig];
                    uint32_t b1 = B[(ns * 8 + grp) * STR + kk + tig + 4];
#pragma unroll
                    for (int mt = 0; mt < 2; mt++)
                        mma8(acc[sel][mt][ns], a[mt][0], a[mt][1], a[mt][2], a[mt][3], b0, b1);
                }
            }
        }
    }
    __syncthreads();

    // stage accumulators in smem (R,Z,Ni,Nh), then combine gates
    float (*E)[64][32] = (float(*)[64][32])dyn;
    if (warp < 6) {
#pragma unroll
        for (int mt = 0; mt < 2; mt++)
#pragma unroll
            for (int ns = 0; ns < 4; ns++)
#pragma unroll
                for (int e = 0; e < 4; e++) {
                    int row = wm * 32 + mt * 16 + grp + ((e >> 1) << 3);
                    int col = ns * 8 + tig * 2 + (e & 1);
                    if (st < 2) E[st][row][col] = acc[0][mt][ns][e];
                    else {
                        E[2][row][col] = acc[0][mt][ns][e];
                        E[3][row][col] = acc[1][mt][ns][e];
                    }
                }
    }
    __syncthreads();

    const float* bi = bih + l * H3q;
    const float* bh = bhh + l * H3q;
#pragma unroll
    for (int e = 0; e < 4; e++) {
        int q = tid + e * 512;
        int m = q >> 5, n = q & 31, col = n0 + n;
        float r  = sigmoidf_(E[0][m][n] + __ldg(bi + col) + __ldg(bh + col));
        float z  = sigmoidf_(E[1][m][n] + __ldg(bi + Hq + col) + __ldg(bh + Hq + col));
        float nn = tanhf(E[2][m][n] + __ldg(bi + 2 * Hq + col)
                         + r * (E[3][m][n] + __ldg(bh + 2 * Hq + col)));
        float hp = __ldcg(&g_hbuf[par ^ 1][l][m][col]);
        g_hgru[l][m][col] = (1.0f - z) * nn + z * hp;
    }
}

// ---------------- 2-rows-per-CTA bitonic sort (ascending, 1024 each) ------------
__device__ __forceinline__ void sort_rows(float* dyn, int l, int pair) {
    const int tid = threadIdx.x;
    const int sub = tid >> 8, tt = tid & 255;
    const int b = pair * 2 + sub;
    float* s = dyn + sub * 1024;
#pragma unroll
    for (int e = 0; e < 4; e++) s[tt + (e << 8)] = __ldcg(&g_hgru[l][b][tt + (e << 8)]);
    __syncthreads();
    for (int k = 2; k <= 1024; k <<= 1) {
        for (int j = k >> 1; j > 0; j >>= 1) {
#pragma unroll
            for (int e = 0; e < 2; e++) {
                int tc = tt + (e << 8);
                int pos = ((tc & ~(j - 1)) << 1) | (tc & (j - 1));
                int q = pos | j;
                bool up = ((pos & k) == 0);
                float a = s[pos], bb = s[q];
                if ((a > bb) == up) { s[pos] = bb; s[q] = a; }
            }
            __syncthreads();
        }
    }
#pragma unroll
    for (int e = 0; e < 4; e++)
        g_sorted[l][b][tt + (e << 8)] = tftrunc(s[tt + (e << 8)]);   // GEMM-only consumer
    __syncthreads();
}

// ---------------- generic FC stage (8 warps of m16n32/m16n16) ----------------
// MODE 0: a0 = [h|sorted] @ w0^T (K=1024, NT=64) -> stored shuffled+tf32
// MODE 1: a1 = a0s @ w1^T        (K=512,  NT=64) -> stored shuffled+tf32
// MODE 2: a2 = relu(a1s @ w2^T)  (K=512,  NT=64) -> linear+tf32
// MODE 3: h' = hgru*sigmoid(a2@w3^T) (K=2048, NT=32) -> hbuf + outs(l==3)
template <int MODE>
__device__ __forceinline__ void fc_stage(float* dyn, int l, int t, int n0,
                                         float* __restrict__ outp)
{
    constexpr int NT = (MODE == 3) ? 32 : 64;
    constexpr int KT = (MODE == 0) ? 1024 : ((MODE == 3) ? 2048 : 512);
    constexpr int NC = KT / KC;
    constexpr int WNC = NT / 2;
    constexpr int NSUB = WNC / 8;
    constexpr int SGF = (64 + NT) * STR;
    constexpr int BN = (NT * 16) / 512;          // B float4 per thread (2 or 1)

    const int tid = threadIdx.x;
    const int warp = tid >> 5, lane = tid & 31;
    const int wm = warp & 3, wn = warp >> 2;     // used when warp < 8
    const int grp = lane >> 2, tig = lane & 3;

    const float* Abase; int astride, aoff = 0;
    if constexpr (MODE == 0)      { Abase = (n0 >= Hq) ? &g_sorted[l][0][0] : &g_hgru[l][0][0]; astride = Hq; }
    else if constexpr (MODE == 1) { Abase = &g_a0[l][0][0]; astride = H2q; aoff = (n0 >> 9) << 9; }
    else if constexpr (MODE == 2) { Abase = &g_a1[l][0][0]; astride = H2q; aoff = (n0 >> 9) << 9; }
    else                          { Abase = &g_a2[l][0][0]; astride = H2q; }

    const float* Wl; int o0;
    if constexpr (MODE == 0)                   { Wl = g_w0 + (size_t)l * Hq * Hq;   o0 = n0 & (Hq - 1); }
    else if constexpr (MODE == 1)              { Wl = g_w1 + (size_t)l * 512 * 512; o0 = n0 & 511; }
    else if constexpr (MODE == 2)              { Wl = g_w2 + (size_t)l * 512 * 512; o0 = n0 & 511; }
    else                                       { Wl = g_w3 + (size_t)l * Hq * H2q;  o0 = n0; }

    auto issue = [&](int c, int s) {
        float* A = dyn + s * SGF;
        float* B = A + 64 * STR;
        const int k0 = c * KC;
#pragma unroll
        for (int i = 0; i < 2; i++) {
            int idx = tid + i * 512;
            int row = idx >> 4, c4 = (idx & 15) << 2;
            cpa16(A + row * STR + c4, Abase + (size_t)row * astride + aoff + k0 + c4);
        }
#pragma unroll
        for (int i = 0; i < BN; i++) {
            int idx = tid + i * 512;
            int br = idx >> 4, c4 = (idx & 15) << 2;
            cpa16(B + br * STR + c4, Wl + (size_t)(o0 + br) * KT + k0 + c4);
        }
        CP_COMMIT();
    };

    float acc[NSUB][4];
#pragma unroll
    for (int i = 0; i < NSUB; i++) { acc[i][0] = acc[i][1] = acc[i][2] = acc[i][3] = 0.f; }

    issue(0, 0); issue(1, 1); issue(2, 2);
    for (int c = 0; c < NC; c++) {
        const int s = c & 3;
        cpwait(NC - 1 - c);
        __syncthreads();
        if (c + 3 < NC) issue(c + 3, (c + 3) & 3);
        if (warp < 8) {
            const float* A = dyn + s * SGF;
            const uint32_t* B = (const uint32_t*)(dyn + s * SGF + 64 * STR);
#pragma unroll
            for (int kk = 0; kk < KC; kk += 8) {
                int r0 = wm * 16 + grp;
                uint32_t a0 = f2tf(A[r0 * STR + kk + tig]);
                uint32_t a1 = f2tf(A[(r0 + 8) * STR + kk + tig]);
                uint32_t a2 = f2tf(A[r0 * STR + kk + tig + 4]);
                uint32_t a3 = f2tf(A[(r0 + 8) * STR + kk + tig + 4]);
#pragma unroll
                for (int ns = 0; ns < NSUB; ns++) {
                    int nb = wn * WNC + ns * 8 + grp;
                    uint32_t b0 = B[nb * STR + kk + tig];
                    uint32_t b1 = B[nb * STR + kk + tig + 4];
                    mma8(acc[ns], a0, a1, a2, a3, b0, b1);
                }
            }
        }
    }

    if (warp < 8) {
#pragma unroll
        for (int ns = 0; ns < NSUB; ns++)
#pragma unroll
            for (int e = 0; e < 4; e++) {
                int row = wm * 16 + grp + ((e >> 1) << 3);
                int cl = wn * WNC + ns * 8 + tig * 2 + (e & 1);
                int cg = n0 + cl;
                float v = acc[ns][e];
                if constexpr (MODE == 0)      g_a0[l][row][4 * (cg & 511) + (cg >> 9)] = tftrunc(v);
                else if constexpr (MODE == 1) g_a1[l][row][4 * (cg & 511) + (cg >> 9)] = tftrunc(v);
                else if constexpr (MODE == 2) g_a2[l][row][cg] = tftrunc(fmaxf(v, 0.0f));
                else {
                    float val = __ldcg(&g_hgru[l][row][cg]) * sigmoidf_(v);
                    g_hbuf[t & 1][l][row][cg] = val;
                    if (l == Lq - 1)
                        outp[((size_t)row * Sq + t) * Hq + cg] = val;
                }
            }
    }
}

// ---------------- the single persistent kernel ----------------
__global__ void __launch_bounds__(NTHR, 1) fss_persist_kernel(
    const float* __restrict__ x, const float* __restrict__ h0,
    const float* __restrict__ Wih, const float* __restrict__ Whh,
    const float* __restrict__ bih, const float* __restrict__ bhh,
    const float* __restrict__ aw0, const float* __restrict__ aw1,
    const float* __restrict__ aw2, const float* __restrict__ aw3,
    float* __restrict__ outp, int out_size)
{
    extern __shared__ float dyn[];
    const int bx = blockIdx.x, tid = threadIdx.x;
    const int gid = bx * NTHR + tid, gsz = NCTA * NTHR;

    // one-time-per-launch weight pre-rounding to tf32
    conv_tf(g_wih, Wih, Lq * H3q * Hq / 4, gid, gsz);
    conv_tf(g_whh, Whh, Lq * H3q * Hq / 4, gid, gsz);
    conv_tf(g_w0,  aw0, Lq * Hq * Hq / 4,  gid, gsz);
    conv_tf(g_w1,  aw1, Lq * 512 * 512 / 4, gid, gsz);
    conv_tf(g_w2,  aw2, Lq * 512 * 512 / 4, gid, gsz);
    conv_tf(g_w3,  aw3, Lq * Hq * H2q / 4, gid, gsz);

    // init hidden into parity-1 buffer (t=0 reads parity (t-1)&1 == 1)
    for (int i = gid; i < Lq * Bq * Hq; i += gsz) {
        int l = i >> 16;
        int k = i & (Hq - 1);
        (&g_hbuf[1][0][0][0])[i] = h0[l * Hq + k];
    }
    gridbar();

    const int l = bx >> 5, idx = bx & 31;
    for (int p = 0; p < NPH; ++p) {
        const int t = p - l;
        if (t >= 0 && t < Sq) {
            gru_stage(dyn, l, t, idx * 32, x, bih, bhh);
            layerbar(l);
            sort_rows(dyn, l, idx);
            layerbar(l);
            fc_stage<0>(dyn, l, t, idx * 64, outp);
            layerbar(l);
            fc_stage<1>(dyn, l, t, idx * 64, outp);
            layerbar(l);
            fc_stage<2>(dyn, l, t, idx * 64, outp);
            layerbar(l);
            fc_stage<3>(dyn, l, t, idx * 32, outp);
        }
        gridbar();
    }

    // final hidden state hT (t=255 -> parity 1), layout (L,B,H)
    if (out_size >= Bq * Sq * Hq + Lq * Bq * Hq) {
        for (int i = gid; i < Lq * Bq * Hq; i += gsz)
            outp[(size_t)Bq * Sq * Hq + i] = __ldcg(&(&g_hbuf[1][0][0][0])[i]);
    }
}

// ---------------- launch ----------------
extern "C" void kernel_launch(void* const* d_in, const int* in_sizes, int n_in,
                              void* d_out, int out_size) {
    (void)in_sizes; (void)n_in;
    cudaFuncSetAttribute(fss_persist_kernel,
                         cudaFuncAttributeMaxDynamicSharedMemorySize, SMEM_BYTES);
    fss_persist_kernel<<<NCTA, NTHR, SMEM_BYTES>>>(
        (const float*)d_in[0], (const float*)d_in[1],
        (const float*)d_in[2], (const float*)d_in[3],
        (const float*)d_in[4], (const float*)d_in[5],
        (const float*)d_in[6], (const float*)d_in[7],
        (const float*)d_in[8], (const float*)d_in[9],
        (float*)d_out, out_size);
}

// round 9
// speedup vs baseline: 2.2515x; 1.3009x over previous
#include <cuda_runtime.h>
#include <cstdint>
#include <cstddef>

#define Bq 64
#define Sq 256
#define Hq 1024
#define Lq 4
#define H2q 2048
#define H3q 3072
#define NCTA 128
#define NTHR 512
#define NPH (Sq + Lq - 1)
#define GA 4096                       // A floats per chunk (64 rows x 64 k)
#define GB 6144                       // GRU B floats per chunk (96 rows x 64 k)
#define GSTG (GA + GB)                // floats per pipeline stage
#define SMEM_BYTES (4 * GSTG * 4)     // 163840 B

// ---------------- persistent device scratch ----------------
__device__ __align__(16) float g_hbuf[2][Lq][Bq][Hq];   // fp32 state (elementwise)
__device__ __align__(16) float g_hbf[2][Lq][Bq * Hq];   // tf32 fragment copy (GEMM A)
__device__ __align__(16) float g_hgru[Lq][Bq][Hq];      // fp32 GRU out (sort + gates)
__device__ __align__(16) float g_hgf[Lq][Bq * Hq];      // fragment copy (fc0 A)
__device__ __align__(16) float g_sf[Lq][Bq * Hq];       // sorted, fragment
__device__ __align__(16) float g_a0f[Lq][Bq * H2q];     // a0 shuffled, fragment
__device__ __align__(16) float g_a1f[Lq][Bq * H2q];     // a1 shuffled, fragment
__device__ __align__(16) float g_a2f[Lq][Bq * H2q];     // relu(a2), fragment
__device__ __align__(16) float g_xf[Sq * Bq * Hq];      // x, fragment per t
// fragment-major tf32 weights
__device__ __align__(16) float g_wihf[Lq * H3q * Hq];
__device__ __align__(16) float g_whhf[Lq * H3q * Hq];
__device__ __align__(16) float g_w0f[Lq * Hq * Hq];
__device__ __align__(16) float g_w1f[Lq * 512 * 512];
__device__ __align__(16) float g_w2f[Lq * 512 * 512];
__device__ __align__(16) float g_w3f[Lq * Hq * H2q];

__device__ unsigned g_cnt = 0;
__device__ volatile unsigned g_gen = 0;
__device__ unsigned g_lcnt[Lq] = {0, 0, 0, 0};
__device__ volatile unsigned g_lgen[Lq] = {0, 0, 0, 0};

// ---------------- helpers ----------------
__device__ __forceinline__ uint32_t f2tf(float f) {
    uint32_t u;
    asm("cvt.rna.tf32.f32 %0, %1;" : "=r"(u) : "f"(f));
    return u;
}
__device__ __forceinline__ float tftrunc(float f) { return __uint_as_float(f2tf(f)); }
__device__ __forceinline__ void mma8(float* c, uint32_t a0, uint32_t a1, uint32_t a2, uint32_t a3,
                                     uint32_t b0, uint32_t b1) {
    asm volatile(
        "mma.sync.aligned.m16n8k8.row.col.f32.tf32.tf32.f32 "
        "{%0,%1,%2,%3},{%4,%5,%6,%7},{%8,%9},{%0,%1,%2,%3};"
        : "+f"(c[0]), "+f"(c[1]), "+f"(c[2]), "+f"(c[3])
        : "r"(a0), "r"(a1), "r"(a2), "r"(a3), "r"(b0), "r"(b1));
}
__device__ __forceinline__ float sigmoidf_(float x) { return 1.0f / (1.0f + __expf(-x)); }

__device__ __forceinline__ void cpa16(void* dst, const void* src) {
    uint32_t d = (uint32_t)__cvta_generic_to_shared(dst);
    asm volatile("cp.async.cg.shared.global [%0], [%1], 16;" :: "r"(d), "l"(src));
}
#define CP_COMMIT() asm volatile("cp.async.commit_group;")
__device__ __forceinline__ void cpwait(int left) {
    if (left >= 2)      asm volatile("cp.async.wait_group 2;");
    else if (left == 1) asm volatile("cp.async.wait_group 1;");
    else                asm volatile("cp.async.wait_group 0;");
}

// fragment index for 64-row A tensors: [kb=col>>3][mb=row>>4][lane32][slot4]
// lane = (row&7)*4 + (col&3); slot = ((col&4)>>2)*2 + ((row&8)>>3)
__device__ __forceinline__ int afidx(int row, int col) {
    return ((((col >> 3) << 2) + (row >> 4)) * 32 + ((row & 7) * 4 + (col & 3))) * 4
         + ((((col & 7) >> 2) << 1) + ((row & 15) >> 3));
}

// ---------------- barriers ----------------
__device__ __forceinline__ void gridbar() {
    __threadfence();
    __syncthreads();
    if (threadIdx.x == 0) {
        unsigned gen = g_gen;
        if (atomicAdd(&g_cnt, 1u) == NCTA - 1) {
            g_cnt = 0;
            __threadfence();
            g_gen = gen + 1;
        } else {
            while (g_gen == gen) __nanosleep(64);
        }
    }
    __syncthreads();
}
__device__ __forceinline__ void layerbar(int l) {
    __threadfence();
    __syncthreads();
    if (threadIdx.x == 0) {
        unsigned gen = g_lgen[l];
        if (atomicAdd(&g_lcnt[l], 1u) == 31) {
            g_lcnt[l] = 0;
            __threadfence();
            g_lgen[l] = gen + 1;
        } else {
            while (g_lgen[l] == gen) __nanosleep(32);
        }
    }
    __syncthreads();
}

// ---------------- weight permute: row-major [N][K] -> fragment-major ----------------
__device__ __forceinline__ void permW(float* dst, const float* src, int N, int K,
                                      int gid, int gsz) {
    const int NB = N >> 3;
    const size_t tot = (size_t)N * K;
    for (size_t i = gid; i < tot; i += gsz) {
        int s = (int)(i & 3);
        int lane = (int)((i >> 2) & 31);
        int kb2 = (int)((i >> 7) & 3);
        size_t hi = i >> 9;
        int nb = (int)(hi % NB);
        int c = (int)(hi / NB);
        int r = nb * 8 + (lane >> 2);
        int k = c * 64 + kb2 * 16 + ((s >> 1) << 3) + ((s & 1) << 2) + (lane & 3);
        dst[i] = tftrunc(__ldg(src + (size_t)r * K + k));
    }
}

// one K64-chunk of m16n32 mma work for one warp (all-register accumulators)
#define FRAG_CHUNK(APTR, BPTR, MB, ACC) { \
    const float* A_ = (APTR); \
    const uint4* Bf_ = (const uint4*)(BPTR); \
    _Pragma("unroll") \
    for (int kb2 = 0; kb2 < 4; kb2++) { \
        uint4 b0_ = Bf_[(0 * 4 + kb2) * 32 + lane]; \
        uint4 b1_ = Bf_[(1 * 4 + kb2) * 32 + lane]; \
        uint4 b2_ = Bf_[(2 * 4 + kb2) * 32 + lane]; \
        uint4 b3_ = Bf_[(3 * 4 + kb2) * 32 + lane]; \
        _Pragma("unroll") \
        for (int pp = 0; pp < 2; pp++) { \
            uint4 aq = *(const uint4*)(A_ + ((kb2 * 2 + pp) * 4 + (MB)) * 128 + lane * 4); \
            mma8(ACC[0], aq.x, aq.y, aq.z, aq.w, pp ? b0_.z : b0_.x, pp ? b0_.w : b0_.y); \
            mma8(ACC[1], aq.x, aq.y, aq.z, aq.w, pp ? b1_.z : b1_.x, pp ? b1_.w : b1_.y); \
            mma8(ACC[2], aq.x, aq.y, aq.z, aq.w, pp ? b2_.z : b2_.x, pp ? b2_.w : b2_.y); \
            mma8(ACC[3], aq.x, aq.y, aq.z, aq.w, pp ? b3_.z : b3_.x, pp ? b3_.w : b3_.y); \
        } \
    } \
}

// ---------------- GRU stage: 32 H-cols/CTA, 12 compute warps (3 streams x 4 m16) ---
__device__ __forceinline__ void gru_stage(float* dyn, int l, int t, int n0,
    const float* __restrict__ bih, const float* __restrict__ bhh)
{
    const int par = t & 1;
    const int tid = threadIdx.x;
    const int warp = tid >> 5, lane = tid & 31;
    const int st = warp >> 2, wm = warp & 3;     // stream, m16 block (warp<12)
    const int grp = lane >> 2, tig = lane & 3;

    const float* Af1 = (l == 0) ? (g_xf + (size_t)t * 65536) : g_hbf[par][l - 1];
    const float* Af2 = g_hbf[par ^ 1][l];
    const float* Wih_ = g_wihf + (size_t)l * H3q * Hq;
    const float* Whh_ = g_whhf + (size_t)l * H3q * Hq;

    auto issue = [&](int c, int sg) {
        float* A = dyn + sg * GSTG;
        float* B = A + GA;
        const float* as = (c < 16) ? (Af1 + (size_t)c * 4096)
                                   : (Af2 + (size_t)(c - 16) * 4096);
        cpa16(A + tid * 4, as + tid * 4);
        cpa16(A + (tid + 512) * 4, as + (tid + 512) * 4);
        const float* wmat = (c < 16) ? Wih_ : Whh_;
        const int cc = c & 15;
#pragma unroll
        for (int s3 = 0; s3 < 3; s3++) {
            const float* ws = wmat + ((size_t)(cc * 384 + s3 * 128 + (n0 >> 3))) * 512;
            cpa16(B + s3 * 2048 + tid * 4, ws + tid * 4);
        }
        CP_COMMIT();
    };

    float acc1[4][4] = {};    // R/Z full, or N(ih) for stream 2
    float acc2[4][4] = {};    // N(hh) for stream 2

    issue(0, 0); issue(1, 1); issue(2, 2);
    for (int c = 0; c < 16; c++) {
        cpwait(31 - c);
        __syncthreads();
        issue(c + 3, (c + 3) & 3);
        if (warp < 12) {
            const int sg = c & 3;
            FRAG_CHUNK(dyn + sg * GSTG, dyn + sg * GSTG + GA + st * 2048, wm, acc1);
        }
    }
    for (int c = 16; c < 32; c++) {
        cpwait(31 - c);
        __syncthreads();
        if (c + 3 < 32) issue(c + 3, (c + 3) & 3);
        if (warp < 12) {
            const int sg = c & 3;
            if (st == 2) {
                FRAG_CHUNK(dyn + sg * GSTG, dyn + sg * GSTG + GA + st * 2048, wm, acc2);
            } else {
                FRAG_CHUNK(dyn + sg * GSTG, dyn + sg * GSTG + GA + st * 2048, wm, acc1);
            }
        }
    }
    __syncthreads();

    // stage accumulators (R,Z,Ni,Nh), then combine gates
    float (*E)[64][32] = (float(*)[64][32])dyn;
    if (warp < 12) {
#pragma unroll
        for (int ns = 0; ns < 4; ns++)
#pragma unroll
            for (int e = 0; e < 4; e++) {
                int row = wm * 16 + grp + ((e >> 1) << 3);
                int col = ns * 8 + tig * 2 + (e & 1);
                if (st < 2) E[st][row][col] = acc1[ns][e];
                else { E[2][row][col] = acc1[ns][e]; E[3][row][col] = acc2[ns][e]; }
            }
    }
    __syncthreads();

    const float* bi = bih + l * H3q;
    const float* bh = bhh + l * H3q;
#pragma unroll
    for (int e = 0; e < 4; e++) {
        int q = tid + e * 512;
        int m = q >> 5, n = q & 31, col = n0 + n;
        float r  = sigmoidf_(E[0][m][n] + __ldg(bi + col) + __ldg(bh + col));
        float z  = sigmoidf_(E[1][m][n] + __ldg(bi + Hq + col) + __ldg(bh + Hq + col));
        float nn = tanhf(E[2][m][n] + __ldg(bi + 2 * Hq + col)
                         + r * (E[3][m][n] + __ldg(bh + 2 * Hq + col)));
        float hp = __ldcg(&g_hbuf[par ^ 1][l][m][col]);
        float hv = (1.0f - z) * nn + z * hp;
        g_hgru[l][m][col] = hv;
        g_hgf[l][afidx(m, col)] = tftrunc(hv);
    }
    __syncthreads();
}

// ---------------- 2-rows-per-CTA bitonic sort (ascending, 1024 each) ------------
__device__ __forceinline__ void sort_rows(float* dyn, int l, int pair) {
    const int tid = threadIdx.x;
    const int sub = tid >> 8, tt = tid & 255;
    const int b = pair * 2 + sub;
    float* s = dyn + sub * 1024;
#pragma unroll
    for (int e = 0; e < 4; e++) s[tt + (e << 8)] = __ldcg(&g_hgru[l][b][tt + (e << 8)]);
    __syncthreads();
    for (int k = 2; k <= 1024; k <<= 1) {
        for (int j = k >> 1; j > 0; j >>= 1) {
#pragma unroll
            for (int e = 0; e < 2; e++) {
                int tc = tt + (e << 8);
                int pos = ((tc & ~(j - 1)) << 1) | (tc & (j - 1));
                int q = pos | j;
                bool up = ((pos & k) == 0);
                float a = s[pos], bb = s[q];
                if ((a > bb) == up) { s[pos] = bb; s[q] = a; }
            }
            __syncthreads();
        }
    }
#pragma unroll
    for (int e = 0; e < 4; e++) {
        int pos = tt + (e << 8);
        g_sf[l][afidx(b, pos)] = tftrunc(s[pos]);
    }
    __syncthreads();
}

// ---------------- generic FC stage (8 compute warps) ----------------
// MODE 0: a0 = [h|sorted]@w0^T (K=1024, NT=64) -> stored shuffled
// MODE 1: a1 = a0s@w1^T        (K=512,  NT=64) -> stored shuffled
// MODE 2: a2 = relu(a1s@w2^T)  (K=512,  NT=64) -> linear
// MODE 3: h' = hgru*sigmoid(a2@w3^T) (K=2048, NT=32) -> hbuf + outs(l==3)
template <int MODE>
__device__ __forceinline__ void fc_stage(float* dyn, int l, int t, int n0,
                                         float* __restrict__ outp)
{
    constexpr int NCH = (MODE == 0) ? 16 : (MODE == 3 ? 32 : 8);
    constexpr int NSUB = (MODE == 3) ? 2 : 4;
    constexpr int BFL = (MODE == 3) ? 2048 : 4096;

    const int tid = threadIdx.x;
    const int warp = tid >> 5, lane = tid & 31;
    const int wm = warp & 3, wn = warp >> 2;      // valid under warp<8
    const int grp = lane >> 2, tig = lane & 3;

    const float* Af;
    if constexpr (MODE == 0)      Af = (n0 >= Hq) ? g_sf[l] : g_hgf[l];
    else if constexpr (MODE == 1) Af = g_a0f[l] + ((size_t)(n0 >> 9) << 15);
    else if constexpr (MODE == 2) Af = g_a1f[l] + ((size_t)(n0 >> 9) << 15);
    else                          Af = g_a2f[l];

    const float* Wf; int o0; int NBALL;
    if constexpr (MODE == 0)      { Wf = g_w0f + (size_t)l * Hq * Hq;   o0 = n0 & (Hq - 1); NBALL = 128; }
    else if constexpr (MODE == 1) { Wf = g_w1f + (size_t)l * 512 * 512; o0 = n0 & 511;      NBALL = 64; }
    else if constexpr (MODE == 2) { Wf = g_w2f + (size_t)l * 512 * 512; o0 = n0 & 511;      NBALL = 64; }
    else                          { Wf = g_w3f + (size_t)l * Hq * H2q;  o0 = n0;            NBALL = 128; }

    auto issue = [&](int c, int sg) {
        float* A = dyn + sg * GSTG;
        float* B = A + GA;
        const float* as = Af + (size_t)c * 4096;
        cpa16(A + tid * 4, as + tid * 4);
        cpa16(A + (tid + 512) * 4, as + (tid + 512) * 4);
        const float* ws = Wf + ((size_t)c * NBALL + (o0 >> 3)) * 512;
        cpa16(B + tid * 4, ws + tid * 4);
        if (BFL == 4096) cpa16(B + (tid + 512) * 4, ws + (tid + 512) * 4);
        CP_COMMIT();
    };

    float acc[NSUB][4];
#pragma unroll
    for (int i = 0; i < NSUB; i++) { acc[i][0] = acc[i][1] = acc[i][2] = acc[i][3] = 0.f; }

    issue(0, 0); issue(1, 1); issue(2, 2);
    for (int c = 0; c < NCH; c++) {
        cpwait(NCH - 1 - c);
        __syncthreads();
        if (c + 3 < NCH) issue(c + 3, (c + 3) & 3);
        if (warp < 8) {
            const int sg = c & 3;
            const float* A_ = dyn + sg * GSTG;
            const uint4* Bf_ = (const uint4*)(dyn + sg * GSTG + GA);
#pragma unroll
            for (int kb2 = 0; kb2 < 4; kb2++) {
                uint4 bq[NSUB];
#pragma unroll
                for (int ns = 0; ns < NSUB; ns++)
                    bq[ns] = Bf_[((wn * NSUB + ns) * 4 + kb2) * 32 + lane];
#pragma unroll
                for (int pp = 0; pp < 2; pp++) {
                    uint4 aq = *(const uint4*)(A_ + ((kb2 * 2 + pp) * 4 + wm) * 128 + lane * 4);
#pragma unroll
                    for (int ns = 0; ns < NSUB; ns++)
                        mma8(acc[ns], aq.x, aq.y, aq.z, aq.w,
                             pp ? bq[ns].z : bq[ns].x, pp ? bq[ns].w : bq[ns].y);
                }
            }
        }
    }
    __syncthreads();

    if (warp < 8) {
#pragma unroll
        for (int ns = 0; ns < NSUB; ns++)
#pragma unroll
            for (int e = 0; e < 4; e++) {
                int row = wm * 16 + grp + ((e >> 1) << 3);
                int cl = wn * (NSUB * 8) + ns * 8 + tig * 2 + (e & 1);
                int cg = n0 + cl;
                float v = acc[ns][e];
                if constexpr (MODE == 0) {
                    int p = 4 * (cg & 511) + (cg >> 9);
                    g_a0f[l][afidx(row, p)] = tftrunc(v);
                } else if constexpr (MODE == 1) {
                    int p = 4 * (cg & 511) + (cg >> 9);
                    g_a1f[l][afidx(row, p)] = tftrunc(v);
                } else if constexpr (MODE == 2) {
                    g_a2f[l][afidx(row, cg)] = tftrunc(fmaxf(v, 0.0f));
                } else {
                    float val = __ldcg(&g_hgru[l][row][cg]) * sigmoidf_(v);
                    g_hbuf[t & 1][l][row][cg] = val;
                    g_hbf[t & 1][l][afidx(row, cg)] = tftrunc(val);
                    if (l == Lq - 1)
                        outp[((size_t)row * Sq + t) * Hq + cg] = val;
                }
            }
    }
    __syncthreads();
}

// ---------------- the single persistent kernel ----------------
__global__ void __launch_bounds__(NTHR, 1) fss_persist_kernel(
    const float* __restrict__ x, const float* __restrict__ h0,
    const float* __restrict__ Wih, const float* __restrict__ Whh,
    const float* __restrict__ bih, const float* __restrict__ bhh,
    const float* __restrict__ aw0, const float* __restrict__ aw1,
    const float* __restrict__ aw2, const float* __restrict__ aw3,
    float* __restrict__ outp, int out_size)
{
    extern __shared__ float dyn[];
    const int bx = blockIdx.x, tid = threadIdx.x;
    const int gid = bx * NTHR + tid, gsz = NCTA * NTHR;

    // --- one-time-per-launch permutes (fragment-major, tf32 pre-rounded) ---
    for (int l0 = 0; l0 < Lq; l0++) {
        permW(g_wihf + (size_t)l0 * H3q * Hq, Wih + (size_t)l0 * H3q * Hq, H3q, Hq, gid, gsz);
        permW(g_whhf + (size_t)l0 * H3q * Hq, Whh + (size_t)l0 * H3q * Hq, H3q, Hq, gid, gsz);
        permW(g_w0f + (size_t)l0 * Hq * Hq,   aw0 + (size_t)l0 * Hq * Hq,  Hq, Hq, gid, gsz);
        permW(g_w1f + (size_t)l0 * 512 * 512, aw1 + (size_t)l0 * 512 * 512, 512, 512, gid, gsz);
        permW(g_w2f + (size_t)l0 * 512 * 512, aw2 + (size_t)l0 * 512 * 512, 512, 512, gid, gsz);
        permW(g_w3f + (size_t)l0 * Hq * H2q,  aw3 + (size_t)l0 * Hq * H2q, Hq, H2q, gid, gsz);
    }
    // x -> per-timestep fragment layout
    for (size_t i = gid; i < (size_t)Sq * 65536; i += gsz) {
        int j = (int)(i & 65535);
        int t = (int)(i >> 16);
        int s = j & 3, lane = (j >> 2) & 31, mb = (j >> 7) & 3, kb = j >> 9;
        int row = mb * 16 + (lane >> 2) + ((s & 1) << 3);
        int col = kb * 8 + (lane & 3) + ((s >> 1) << 2);
        g_xf[i] = tftrunc(__ldg(x + ((size_t)row * Sq + t) * Hq + col));
    }
    // h0 -> parity-1 buffers (linear + fragment); t=0 reads parity 1
    for (int i = gid; i < Lq * 65536; i += gsz) {
        int l0 = i >> 16, j = i & 65535;
        int b = j >> 10, k = j & (Hq - 1);
        g_hbuf[1][l0][b][k] = h0[l0 * Hq + k];
        int s = j & 3, lane = (j >> 2) & 31, kb = j >> 9;
        int col = kb * 8 + (lane & 3) + ((s >> 1) << 2);
        g_hbf[1][l0][j] = tftrunc(h0[l0 * Hq + col]);
    }
    gridbar();

    const int l = bx >> 5, idx = bx & 31;
    for (int p = 0; p < NPH; ++p) {
        const int t = p - l;
        if (t >= 0 && t < Sq) {
            gru_stage(dyn, l, t, idx * 32, bih, bhh);
            layerbar(l);
            sort_rows(dyn, l, idx);
            layerbar(l);
            fc_stage<0>(dyn, l, t, idx * 64, outp);
            layerbar(l);
            fc_stage<1>(dyn, l, t, idx * 64, outp);
            layerbar(l);
            fc_stage<2>(dyn, l, t, idx * 64, outp);
            layerbar(l);
            fc_stage<3>(dyn, l, t, idx * 32, outp);
        }
        gridbar();
    }

    // final hidden state hT (t=255 -> parity 1), layout (L,B,H)
    if (out_size >= Bq * Sq * Hq + Lq * Bq * Hq) {
        for (int i = gid; i < Lq * Bq * Hq; i += gsz)
            outp[(size_t)Bq * Sq * Hq + i] = __ldcg(&(&g_hbuf[1][0][0][0])[i]);
    }
}

// ---------------- launch ----------------
extern "C" void kernel_launch(void* const* d_in, const int* in_sizes, int n_in,
                              void* d_out, int out_size) {
    (void)in_sizes; (void)n_in;
    cudaFuncSetAttribute(fss_persist_kernel,
                         cudaFuncAttributeMaxDynamicSharedMemorySize, SMEM_BYTES);
    fss_persist_kernel<<<NCTA, NTHR, SMEM_BYTES>>>(
        (const float*)d_in[0], (const float*)d_in[1],
        (const float*)d_in[2], (const float*)d_in[3],
        (const float*)d_in[4], (const float*)d_in[5],
        (const float*)d_in[6], (const float*)d_in[7],
        (const float*)d_in[8], (const float*)d_in[9],
        (float*)d_out, out_size);
}